// round 2
// baseline (speedup 1.0000x reference)
#include <cuda_runtime.h>
#include <cuda_bf16.h>
#include <cstdint>

// Problem constants
#define NROWS 262144
#define CIN   256
#define MID   64
#define KOFF  9
#define EPS   1e-5f

// Scratch (device globals; allocation is forbidden)
__device__ float g_h2[(size_t)NROWS * MID];   // after conv1+bn2+relu
__device__ float g_h4[(size_t)NROWS * MID];   // after conv2+bn3+relu
__device__ int   g_mask_mode;                 // 0=int32 1=uint8 2=float32 3=bf16

// ---------------------------------------------------------------------------
// Mask dtype probe (unchanged)
// ---------------------------------------------------------------------------
__global__ void kDetect(const unsigned char* __restrict__ m) {
    if (threadIdx.x != 0 || blockIdx.x != 0) return;
    int saw3F_at1 = 0, saw3F = 0, sawNZ_nm4 = 0;
    for (int i = 0; i < 4096; i++) {
        unsigned char b = m[i];
        if (b == 0x3F) { saw3F = 1; if ((i & 3) == 1) saw3F_at1 = 1; }
        else if (b != 0 && (i & 3) != 0) sawNZ_nm4 = 1;
    }
    int mode;
    if (saw3F_at1)      mode = 3;
    else if (saw3F)     mode = 2;
    else if (sawNZ_nm4) mode = 1;
    else                mode = 0;
    g_mask_mode = mode;
}

__device__ __forceinline__ bool mask_on(const void* p, size_t i, int mode) {
    switch (mode) {
        case 1:  return ((const unsigned char*)p)[i] != 0;
        case 2:  return ((const float*)p)[i] != 0.0f;
        case 3:  return ((const unsigned short*)p)[i] != 0;
        default: return ((const int*)p)[i] != 0;
    }
}

// Micro-tile geometry: BM=256, BN=64, 128 threads, 8 rows x 16 cols per thread.
// tx = tid & 3 (col group of 16), ty = tid >> 2 (row group of 8).

#define FMA_TILE(acc, Arow, Brow, aoff, boff)                                  \
    {                                                                          \
        float4 a0 = *reinterpret_cast<const float4*>((Arow) + (aoff));         \
        float4 a1 = *reinterpret_cast<const float4*>((Arow) + (aoff) + 4);     \
        float4 b0 = *reinterpret_cast<const float4*>((Brow) + (boff));         \
        float4 b1 = *reinterpret_cast<const float4*>((Brow) + (boff) + 4);     \
        float4 b2 = *reinterpret_cast<const float4*>((Brow) + (boff) + 8);     \
        float4 b3 = *reinterpret_cast<const float4*>((Brow) + (boff) + 12);    \
        float a[8] = {a0.x,a0.y,a0.z,a0.w,a1.x,a1.y,a1.z,a1.w};                \
        float b[16] = {b0.x,b0.y,b0.z,b0.w,b1.x,b1.y,b1.z,b1.w,                \
                       b2.x,b2.y,b2.z,b2.w,b3.x,b3.y,b3.z,b3.w};               \
        _Pragma("unroll")                                                      \
        for (int i_ = 0; i_ < 8; i_++)                                         \
            _Pragma("unroll")                                                  \
            for (int j_ = 0; j_ < 16; j_++)                                    \
                acc[i_][j_] += a[i_] * b[j_];                                  \
    }

// ---------------------------------------------------------------------------
// Kernel A: h2 = relu(bn2( relu(bn1(x)) @ w1 + b1 ))     [N,256]->[N,64]
// ---------------------------------------------------------------------------
__global__ void __launch_bounds__(128, 2)
kA(const float* __restrict__ x,
   const float* __restrict__ g1, const float* __restrict__ be1,
   const float* __restrict__ mu1, const float* __restrict__ va1,
   const float* __restrict__ w1, const float* __restrict__ b1,
   const float* __restrict__ g2, const float* __restrict__ be2,
   const float* __restrict__ mu2, const float* __restrict__ va2)
{
    __shared__ float Xs[32][260];     // transposed x_preact tile [k][m], BM=256
    __shared__ float Ws[32][64];      // w1 tile [k][n]
    __shared__ float s1[CIN], t1[CIN];
    __shared__ float s2[MID], u2[MID];

    const int tid = threadIdx.x;
    for (int c = tid; c < CIN; c += 128) {
        float s = g1[c] * rsqrtf(va1[c] + EPS);
        s1[c] = s; t1[c] = be1[c] - mu1[c] * s;
    }
    if (tid < MID) {
        float s = g2[tid] * rsqrtf(va2[tid] + EPS);
        s2[tid] = s;
        u2[tid] = b1[tid] * s + (be2[tid] - mu2[tid] * s);
    }

    const int m0 = blockIdx.x * 256;
    const int tx = tid & 3, ty = tid >> 2;
    float acc[8][16] = {};

    for (int kk = 0; kk < CIN; kk += 32) {
        __syncthreads();
        // x tile: 2 rows per thread, bn1+relu on the fly, store transposed
        #pragma unroll
        for (int rr = 0; rr < 2; rr++) {
            const int mloc = rr * 128 + tid;
            const float4* xr = reinterpret_cast<const float4*>(
                x + (size_t)(m0 + mloc) * CIN + kk);
            #pragma unroll
            for (int i = 0; i < 8; i++) {
                float4 v = xr[i];
                int c = kk + i * 4;
                Xs[i*4+0][mloc] = fmaxf(v.x * s1[c+0] + t1[c+0], 0.0f);
                Xs[i*4+1][mloc] = fmaxf(v.y * s1[c+1] + t1[c+1], 0.0f);
                Xs[i*4+2][mloc] = fmaxf(v.z * s1[c+2] + t1[c+2], 0.0f);
                Xs[i*4+3][mloc] = fmaxf(v.w * s1[c+3] + t1[c+3], 0.0f);
            }
        }
        // w1 tile [32][64] contiguous: 512 float4, 4 per thread
        {
            const float4* wr = reinterpret_cast<const float4*>(w1 + (size_t)kk * MID);
            float4* ws = reinterpret_cast<float4*>(&Ws[0][0]);
            #pragma unroll
            for (int i = 0; i < 4; i++) ws[tid + i * 128] = wr[tid + i * 128];
        }
        __syncthreads();

        #pragma unroll 4
        for (int k = 0; k < 32; k++) {
            FMA_TILE(acc, &Xs[k][0], &Ws[k][0], ty * 8, tx * 16);
        }
    }

    // epilogue: +b1 folded, bn2+relu, store h2
    #pragma unroll
    for (int i = 0; i < 8; i++) {
        int r = m0 + ty * 8 + i;
        float o[16];
        #pragma unroll
        for (int j = 0; j < 16; j++) {
            int cl = tx * 16 + j;
            o[j] = fmaxf(acc[i][j] * s2[cl] + u2[cl], 0.0f);
        }
        float4* dst = reinterpret_cast<float4*>(g_h2 + (size_t)r * MID + tx * 16);
        #pragma unroll
        for (int q = 0; q < 4; q++)
            dst[q] = make_float4(o[q*4+0], o[q*4+1], o[q*4+2], o[q*4+3]);
    }
}

// ---------------------------------------------------------------------------
// Kernel B: gather-GEMM over 9 offsets, then h4 = relu(bn3(h3 + b2))
// ---------------------------------------------------------------------------
__global__ void __launch_bounds__(128, 2)
kB(const float* __restrict__ w2, const float* __restrict__ b2,
   const float* __restrict__ g3, const float* __restrict__ be3,
   const float* __restrict__ mu3, const float* __restrict__ va3,
   const int* __restrict__ nbr, const void* __restrict__ maskp)
{
    extern __shared__ float sm[];
    float* Gs  = sm;                 // [64][260] transposed gathered tile
    float* W2s = sm + 64 * 260;      // [64][64]
    float* s3  = W2s + 64 * 64;      // [64]
    float* u3  = s3 + 64;            // [64]

    const int tid = threadIdx.x;
    if (tid < MID) {
        float s = g3[tid] * rsqrtf(va3[tid] + EPS);
        s3[tid] = s;
        u3[tid] = b2[tid] * s + (be3[tid] - mu3[tid] * s);
    }

    const int m0 = blockIdx.x * 256;
    const int mode = g_mask_mode;
    const int tx = tid & 3, ty = tid >> 2;
    float acc[8][16] = {};

    for (int k = 0; k < KOFF; k++) {
        __syncthreads();
        // w2[k] tile: 64x64 contiguous = 1024 float4, 8 per thread
        {
            const float4* wr = reinterpret_cast<const float4*>(w2 + (size_t)k * 4096);
            float4* ws = reinterpret_cast<float4*>(W2s);
            #pragma unroll
            for (int i = 0; i < 8; i++) ws[tid + i * 128] = wr[tid + i * 128];
        }
        // gather 2 rows per thread, store transposed
        #pragma unroll
        for (int rr = 0; rr < 2; rr++) {
            const int mloc = rr * 128 + tid;
            size_t e = (size_t)(m0 + mloc) * KOFF + k;
            int idx = nbr[e];
            bool on = mask_on(maskp, e, mode);
            const float4* hr = reinterpret_cast<const float4*>(g_h2 + (size_t)idx * MID);
            #pragma unroll
            for (int i = 0; i < 16; i++) {
                float4 v = make_float4(0.f, 0.f, 0.f, 0.f);
                if (on) v = hr[i];
                Gs[(i*4+0)*260 + mloc] = v.x;
                Gs[(i*4+1)*260 + mloc] = v.y;
                Gs[(i*4+2)*260 + mloc] = v.z;
                Gs[(i*4+3)*260 + mloc] = v.w;
            }
        }
        __syncthreads();

        #pragma unroll 4
        for (int c = 0; c < 64; c++) {
            FMA_TILE(acc, &Gs[c * 260], &W2s[c * 64], ty * 8, tx * 16);
        }
    }

    // epilogue: +b2 folded, bn3+relu, store h4
    #pragma unroll
    for (int i = 0; i < 8; i++) {
        int r = m0 + ty * 8 + i;
        float o[16];
        #pragma unroll
        for (int j = 0; j < 16; j++) {
            int cl = tx * 16 + j;
            o[j] = fmaxf(acc[i][j] * s3[cl] + u3[cl], 0.0f);
        }
        float4* dst = reinterpret_cast<float4*>(g_h4 + (size_t)r * MID + tx * 16);
        #pragma unroll
        for (int q = 0; q < 4; q++)
            dst[q] = make_float4(o[q*4+0], o[q*4+1], o[q*4+2], o[q*4+3]);
    }
}

// ---------------------------------------------------------------------------
// Kernel C: out = h4 @ w3 + b3 + relu(bn1(x))   [N,64]->[N,256]
// Grid (rowtiles, 4 coltiles of 64).
// ---------------------------------------------------------------------------
__global__ void __launch_bounds__(128, 2)
kC(const float* __restrict__ x,
   const float* __restrict__ g1, const float* __restrict__ be1,
   const float* __restrict__ mu1, const float* __restrict__ va1,
   const float* __restrict__ w3, const float* __restrict__ b3,
   float* __restrict__ out)
{
    extern __shared__ float sm[];
    float* Hs  = sm;                  // [64][260] transposed h4 tile
    float* W3s = sm + 64 * 260;       // [64][64]
    float* s1c = W3s + 64 * 64;
    float* t1c = s1c + 64;
    float* b3c = t1c + 64;

    const int tid = threadIdx.x;
    const int m0 = blockIdx.x * 256;
    const int c0 = blockIdx.y * 64;

    if (tid < 64) {
        int c = c0 + tid;
        float s = g1[c] * rsqrtf(va1[c] + EPS);
        s1c[tid] = s; t1c[tid] = be1[c] - mu1[c] * s; b3c[tid] = b3[c];
    }
    // h4 tile transposed: 2 rows per thread
    #pragma unroll
    for (int rr = 0; rr < 2; rr++) {
        const int mloc = rr * 128 + tid;
        const float4* hr = reinterpret_cast<const float4*>(
            g_h4 + (size_t)(m0 + mloc) * MID);
        #pragma unroll
        for (int i = 0; i < 16; i++) {
            float4 v = hr[i];
            Hs[(i*4+0)*260 + mloc] = v.x;
            Hs[(i*4+1)*260 + mloc] = v.y;
            Hs[(i*4+2)*260 + mloc] = v.z;
            Hs[(i*4+3)*260 + mloc] = v.w;
        }
    }
    // w3 slice [64 rows][cols c0..c0+63]: 1024 float4, 8 per thread
    {
        #pragma unroll
        for (int i = 0; i < 8; i++) {
            int lin = tid + i * 128;
            int c = lin >> 4, n4 = lin & 15;
            float4 v = *reinterpret_cast<const float4*>(
                w3 + (size_t)c * CIN + c0 + n4 * 4);
            *reinterpret_cast<float4*>(&W3s[c * 64 + n4 * 4]) = v;
        }
    }
    __syncthreads();

    const int tx = tid & 3, ty = tid >> 2;
    float acc[8][16] = {};
    #pragma unroll 4
    for (int c = 0; c < 64; c++) {
        FMA_TILE(acc, &Hs[c * 260], &W3s[c * 64], ty * 8, tx * 16);
    }

    // epilogue: + b3 + shortcut (recompute bn1+relu from x), store out
    #pragma unroll
    for (int i = 0; i < 8; i++) {
        int r = m0 + ty * 8 + i;
        const float4* xr = reinterpret_cast<const float4*>(
            x + (size_t)r * CIN + c0 + tx * 16);
        float4 xv4[4] = {xr[0], xr[1], xr[2], xr[3]};
        const float* xv = reinterpret_cast<const float*>(xv4);
        float o[16];
        #pragma unroll
        for (int j = 0; j < 16; j++) {
            int cl = tx * 16 + j;
            o[j] = acc[i][j] + b3c[cl] + fmaxf(xv[j] * s1c[cl] + t1c[cl], 0.0f);
        }
        float4* dst = reinterpret_cast<float4*>(out + (size_t)r * CIN + c0 + tx * 16);
        #pragma unroll
        for (int q = 0; q < 4; q++)
            dst[q] = make_float4(o[q*4+0], o[q*4+1], o[q*4+2], o[q*4+3]);
    }
}

// ---------------------------------------------------------------------------
extern "C" void kernel_launch(void* const* d_in, const int* in_sizes, int n_in,
                              void* d_out, int out_size)
{
    const float* x        = (const float*)d_in[0];
    const float* bn1_g    = (const float*)d_in[1];
    const float* bn1_b    = (const float*)d_in[2];
    const float* bn1_m    = (const float*)d_in[3];
    const float* bn1_v    = (const float*)d_in[4];
    const float* w1       = (const float*)d_in[5];
    const float* b1       = (const float*)d_in[6];
    const float* bn2_g    = (const float*)d_in[7];
    const float* bn2_b    = (const float*)d_in[8];
    const float* bn2_m    = (const float*)d_in[9];
    const float* bn2_v    = (const float*)d_in[10];
    const float* w2       = (const float*)d_in[11];
    const float* b2       = (const float*)d_in[12];
    const float* bn3_g    = (const float*)d_in[13];
    const float* bn3_b    = (const float*)d_in[14];
    const float* bn3_m    = (const float*)d_in[15];
    const float* bn3_v    = (const float*)d_in[16];
    const float* w3       = (const float*)d_in[17];
    const float* b3       = (const float*)d_in[18];
    const int*   nbr_idx  = (const int*)d_in[19];
    const void*  nbr_mask = (const void*)d_in[20];
    float* out = (float*)d_out;

    const size_t SMB = (size_t)(64 * 260 + 64 * 64 + 128) * sizeof(float);
    const size_t SMC = (size_t)(64 * 260 + 64 * 64 + 192) * sizeof(float);
    cudaFuncSetAttribute(kB, cudaFuncAttributeMaxDynamicSharedMemorySize, (int)SMB);
    cudaFuncSetAttribute(kC, cudaFuncAttributeMaxDynamicSharedMemorySize, (int)SMC);

    kDetect<<<1, 1>>>((const unsigned char*)nbr_mask);
    kA<<<NROWS / 256, 128>>>(x, bn1_g, bn1_b, bn1_m, bn1_v, w1, b1,
                             bn2_g, bn2_b, bn2_m, bn2_v);
    kB<<<NROWS / 256, 128, SMB>>>(w2, b2, bn3_g, bn3_b, bn3_m, bn3_v,
                                  nbr_idx, nbr_mask);
    kC<<<dim3(NROWS / 256, 4), 128, SMC>>>(x, bn1_g, bn1_b, bn1_m, bn1_v,
                                           w3, b3, out);
    (void)in_sizes; (void)n_in; (void)out_size;
}

// round 4
// speedup vs baseline: 1.4737x; 1.4737x over previous
#include <cuda_runtime.h>
#include <cuda_bf16.h>
#include <cstdint>

#define NROWS 262144
#define CIN   256
#define MID   64
#define KOFF  9
#define EPS   1e-5f

// Pre-split bf16 tables for intermediates (device globals; no allocs allowed)
__device__ unsigned short g_h2hi[(size_t)NROWS * MID];
__device__ unsigned short g_h2lo[(size_t)NROWS * MID];
__device__ unsigned short g_h4hi[(size_t)NROWS * MID];
__device__ unsigned short g_h4lo[(size_t)NROWS * MID];
__device__ int g_mask_mode;

__device__ __forceinline__ uint32_t smem_to_u32(const void* p) {
    uint32_t a;
    asm("{ .reg .u64 t; cvta.to.shared.u64 t, %1; cvt.u32.u64 %0, t; }"
        : "=r"(a) : "l"(p));
    return a;
}

#define LDSM4(r, a)                                                            \
    asm volatile("ldmatrix.sync.aligned.m8n8.x4.shared.b16 {%0,%1,%2,%3}, [%4];" \
        : "=r"((r)[0]), "=r"((r)[1]), "=r"((r)[2]), "=r"((r)[3]) : "r"(a))

#define MMA_BF16(d, a, b)                                                      \
    asm volatile("mma.sync.aligned.m16n8k16.row.col.f32.bf16.bf16.f32 "        \
        "{%0,%1,%2,%3}, {%4,%5,%6,%7}, {%8,%9}, {%0,%1,%2,%3};"                \
        : "+f"((d)[0]), "+f"((d)[1]), "+f"((d)[2]), "+f"((d)[3])               \
        : "r"((a)[0]), "r"((a)[1]), "r"((a)[2]), "r"((a)[3]),                  \
          "r"((b)[0]), "r"((b)[1]))

__device__ __forceinline__ void split2(float v0, float v1, uint32_t& hi, uint32_t& lo) {
    __nv_bfloat16 h0 = __float2bfloat16(v0), h1 = __float2bfloat16(v1);
    __nv_bfloat16 l0 = __float2bfloat16(v0 - __bfloat162float(h0));
    __nv_bfloat16 l1 = __float2bfloat16(v1 - __bfloat162float(h1));
    hi = (uint32_t)__bfloat16_as_ushort(h0) | ((uint32_t)__bfloat16_as_ushort(h1) << 16);
    lo = (uint32_t)__bfloat16_as_ushort(l0) | ((uint32_t)__bfloat16_as_ushort(l1) << 16);
}
__device__ __forceinline__ void split1(float v, unsigned short& h, unsigned short& l) {
    __nv_bfloat16 hb = __float2bfloat16(v);
    __nv_bfloat16 lb = __float2bfloat16(v - __bfloat162float(hb));
    h = __bfloat16_as_ushort(hb); l = __bfloat16_as_ushort(lb);
}

// ---------------------------------------------------------------------------
// Mask dtype probe
// ---------------------------------------------------------------------------
__global__ void kDetect(const unsigned char* __restrict__ m) {
    if (threadIdx.x != 0 || blockIdx.x != 0) return;
    int saw3F_at1 = 0, saw3F = 0, sawNZ_nm4 = 0;
    for (int i = 0; i < 4096; i++) {
        unsigned char b = m[i];
        if (b == 0x3F) { saw3F = 1; if ((i & 3) == 1) saw3F_at1 = 1; }
        else if (b != 0 && (i & 3) != 0) sawNZ_nm4 = 1;
    }
    int mode;
    if (saw3F_at1)      mode = 3;
    else if (saw3F)     mode = 2;
    else if (sawNZ_nm4) mode = 1;
    else                mode = 0;
    g_mask_mode = mode;
}
__device__ __forceinline__ bool mask_on(const void* p, size_t i, int mode) {
    switch (mode) {
        case 1:  return ((const unsigned char*)p)[i] != 0;
        case 2:  return ((const float*)p)[i] != 0.0f;
        case 3:  return ((const unsigned short*)p)[i] != 0;
        default: return ((const int*)p)[i] != 0;
    }
}

// SMEM byte offsets. A tiles: [128 rows][72 bf16] (144B stride). B: [64 n][72 bf16].
#define AHI 0
#define ALO 18432
#define BHI 36864
#define BLO 46080
#define PAR 55296
#define ASTRIDE 144

// One 64-deep K chunk: warp computes 16x64, 3-MMA hi/lo scheme.
// aoff/boff0: per-thread ldmatrix byte offsets (precomputed, k-invariant).
__device__ __forceinline__ void gemm_chunk(uint32_t sb, uint32_t aoff, uint32_t boff0,
                                           float acc[8][4]) {
    #pragma unroll
    for (int ks = 0; ks < 4; ks++) {
        uint32_t ah[4], al[4];
        LDSM4(ah, sb + AHI + aoff + ks * 32);
        LDSM4(al, sb + ALO + aoff + ks * 32);
        uint32_t bh[16], bl[16];
        #pragma unroll
        for (int p = 0; p < 4; p++) {
            LDSM4(bh + 4 * p, sb + BHI + boff0 + p * (16 * ASTRIDE) + ks * 32);
            LDSM4(bl + 4 * p, sb + BLO + boff0 + p * (16 * ASTRIDE) + ks * 32);
        }
        #pragma unroll
        for (int nt = 0; nt < 8; nt++) {
            const uint32_t* fh = bh + (nt >> 1) * 4 + (nt & 1) * 2;
            const uint32_t* fl = bl + (nt >> 1) * 4 + (nt & 1) * 2;
            MMA_BF16(acc[nt], ah, fh);
            MMA_BF16(acc[nt], ah, fl);
            MMA_BF16(acc[nt], al, fh);
        }
    }
}

// Transpose a [64k x 64n] f32 weight chunk into split-bf16 B tiles [n][k].
__device__ __forceinline__ void build_B(char* smem, const float* __restrict__ wsrc,
                                        int ldw, int tid) {
    const int kr = tid >> 2, ns = (tid & 3) * 16;
    const float4* wr = reinterpret_cast<const float4*>(wsrc + (size_t)kr * ldw + ns);
    #pragma unroll
    for (int q = 0; q < 4; q++) {
        float4 v = wr[q];
        float e[4] = {v.x, v.y, v.z, v.w};
        #pragma unroll
        for (int j = 0; j < 4; j++) {
            int n = ns + q * 4 + j;
            unsigned short h, l; split1(e[j], h, l);
            *(unsigned short*)(smem + BHI + n * ASTRIDE + kr * 2) = h;
            *(unsigned short*)(smem + BLO + n * ASTRIDE + kr * 2) = l;
        }
    }
}

// Per-thread ldmatrix offsets.
__device__ __forceinline__ uint32_t a_off(int wr0, int lane) {
    int row = wr0 + (lane & 7) + ((lane >> 3) & 1) * 8;
    return row * ASTRIDE + (lane >> 4) * 16;
}
__device__ __forceinline__ uint32_t b_off(int lane) {
    int n = (lane & 7) + (lane >> 4) * 8;
    return n * ASTRIDE + ((lane >> 3) & 1) * 16;
}

// ---------------------------------------------------------------------------
// Kernel A: h2 = relu(bn2( relu(bn1(x)) @ w1 + b1 )) -> g_h2hi/lo
// ---------------------------------------------------------------------------
__global__ void __launch_bounds__(256)
kA(const float* __restrict__ x,
   const float* __restrict__ g1, const float* __restrict__ be1,
   const float* __restrict__ mu1, const float* __restrict__ va1,
   const float* __restrict__ w1, const float* __restrict__ b1,
   const float* __restrict__ g2, const float* __restrict__ be2,
   const float* __restrict__ mu2, const float* __restrict__ va2)
{
    extern __shared__ char smem[];
    const uint32_t sb = smem_to_u32(smem);
    float* s1 = (float*)(smem + PAR);
    float* t1 = s1 + 256; float* s2 = t1 + 256; float* u2 = s2 + 64;

    const int tid = threadIdx.x, lane = tid & 31, wid = tid >> 5;
    if (tid < 256) {
        float s = g1[tid] * rsqrtf(va1[tid] + EPS);
        s1[tid] = s; t1[tid] = be1[tid] - mu1[tid] * s;
    }
    if (tid < 64) {
        float s = g2[tid] * rsqrtf(va2[tid] + EPS);
        s2[tid] = s;
        u2[tid] = b1[tid] * s + (be2[tid] - mu2[tid] * s);
    }

    const int m0 = blockIdx.x * 128;
    const int row = tid >> 1, half = tid & 1;
    const float* xrow = x + (size_t)(m0 + row) * CIN + half * 32;
    const uint32_t aoff = a_off(wid * 16, lane), boff = b_off(lane);
    float acc[8][4] = {};

    for (int ch = 0; ch < 4; ch++) {
        __syncthreads();
        // A tile: bn1+relu, split, padded layout
        {
            const float4* xr = reinterpret_cast<const float4*>(xrow + ch * 64);
            #pragma unroll
            for (int q = 0; q < 8; q++) {
                float4 v = xr[q];
                int cg = ch * 64 + half * 32 + q * 4;
                float a0 = fmaxf(v.x * s1[cg+0] + t1[cg+0], 0.0f);
                float a1 = fmaxf(v.y * s1[cg+1] + t1[cg+1], 0.0f);
                float a2 = fmaxf(v.z * s1[cg+2] + t1[cg+2], 0.0f);
                float a3 = fmaxf(v.w * s1[cg+3] + t1[cg+3], 0.0f);
                uint32_t h01, l01, h23, l23;
                split2(a0, a1, h01, l01); split2(a2, a3, h23, l23);
                int bo = row * ASTRIDE + half * 64 + q * 8;
                *(uint32_t*)(smem + AHI + bo)     = h01;
                *(uint32_t*)(smem + AHI + bo + 4) = h23;
                *(uint32_t*)(smem + ALO + bo)     = l01;
                *(uint32_t*)(smem + ALO + bo + 4) = l23;
            }
        }
        build_B(smem, w1 + (size_t)(ch * 64) * MID, MID, tid);
        __syncthreads();
        gemm_chunk(sb, aoff, boff, acc);
    }

    // Epilogue: bn2+relu, split, store
    const int r0 = m0 + wid * 16 + (lane >> 2);
    #pragma unroll
    for (int nt = 0; nt < 8; nt++) {
        int c0 = nt * 8 + (lane & 3) * 2;
        float v00 = fmaxf(acc[nt][0] * s2[c0]   + u2[c0],   0.0f);
        float v01 = fmaxf(acc[nt][1] * s2[c0+1] + u2[c0+1], 0.0f);
        float v10 = fmaxf(acc[nt][2] * s2[c0]   + u2[c0],   0.0f);
        float v11 = fmaxf(acc[nt][3] * s2[c0+1] + u2[c0+1], 0.0f);
        uint32_t h0, l0, h1, l1;
        split2(v00, v01, h0, l0); split2(v10, v11, h1, l1);
        *(uint32_t*)(g_h2hi + (size_t)r0 * MID + c0)       = h0;
        *(uint32_t*)(g_h2lo + (size_t)r0 * MID + c0)       = l0;
        *(uint32_t*)(g_h2hi + (size_t)(r0+8) * MID + c0)   = h1;
        *(uint32_t*)(g_h2lo + (size_t)(r0+8) * MID + c0)   = l1;
    }
}

// ---------------------------------------------------------------------------
// Kernel B: gather-GEMM over 9 offsets, h4 = relu(bn3(Σ gathered@w2 + b2))
// ---------------------------------------------------------------------------
__global__ void __launch_bounds__(256)
kB(const float* __restrict__ w2, const float* __restrict__ b2,
   const float* __restrict__ g3, const float* __restrict__ be3,
   const float* __restrict__ mu3, const float* __restrict__ va3,
   const int* __restrict__ nbr, const void* __restrict__ maskp)
{
    extern __shared__ char smem[];
    const uint32_t sb = smem_to_u32(smem);
    float* s3 = (float*)(smem + PAR);
    float* u3 = s3 + 64;

    const int tid = threadIdx.x, lane = tid & 31, wid = tid >> 5;
    if (tid < 64) {
        float s = g3[tid] * rsqrtf(va3[tid] + EPS);
        s3[tid] = s;
        u3[tid] = b2[tid] * s + (be3[tid] - mu3[tid] * s);
    }

    const int m0 = blockIdx.x * 128;
    const int row = tid >> 1, half = tid & 1;
    const int mode = g_mask_mode;
    const uint32_t aoff = a_off(wid * 16, lane), boff = b_off(lane);
    float acc[8][4] = {};

    for (int k = 0; k < KOFF; k++) {
        __syncthreads();
        build_B(smem, w2 + (size_t)k * 4096, MID, tid);
        // gather pre-split h2 rows
        {
            size_t e = (size_t)(m0 + row) * KOFF + k;
            int idx = nbr[e];
            bool on = mask_on(maskp, e, mode);
            const uint4* hp = reinterpret_cast<const uint4*>(g_h2hi + (size_t)idx * MID + half * 32);
            const uint4* lp = reinterpret_cast<const uint4*>(g_h2lo + (size_t)idx * MID + half * 32);
            const uint4 z = make_uint4(0, 0, 0, 0);
            #pragma unroll
            for (int q = 0; q < 4; q++) {
                uint4 vh = on ? hp[q] : z;
                uint4 vl = on ? lp[q] : z;
                int bo = row * ASTRIDE + half * 64 + q * 16;
                *(uint4*)(smem + AHI + bo) = vh;
                *(uint4*)(smem + ALO + bo) = vl;
            }
        }
        __syncthreads();
        gemm_chunk(sb, aoff, boff, acc);
    }

    const int r0 = m0 + wid * 16 + (lane >> 2);
    #pragma unroll
    for (int nt = 0; nt < 8; nt++) {
        int c0 = nt * 8 + (lane & 3) * 2;
        float v00 = fmaxf(acc[nt][0] * s3[c0]   + u3[c0],   0.0f);
        float v01 = fmaxf(acc[nt][1] * s3[c0+1] + u3[c0+1], 0.0f);
        float v10 = fmaxf(acc[nt][2] * s3[c0]   + u3[c0],   0.0f);
        float v11 = fmaxf(acc[nt][3] * s3[c0+1] + u3[c0+1], 0.0f);
        uint32_t h0, l0, h1, l1;
        split2(v00, v01, h0, l0); split2(v10, v11, h1, l1);
        *(uint32_t*)(g_h4hi + (size_t)r0 * MID + c0)       = h0;
        *(uint32_t*)(g_h4lo + (size_t)r0 * MID + c0)       = l0;
        *(uint32_t*)(g_h4hi + (size_t)(r0+8) * MID + c0)   = h1;
        *(uint32_t*)(g_h4lo + (size_t)(r0+8) * MID + c0)   = l1;
    }
}

// ---------------------------------------------------------------------------
// Kernel C: out = h4 @ w3 + b3 + relu(bn1(x))
// Grid (4 colslices, NROWS/128 rowtiles): same row-tile's 4 slices run together.
// ---------------------------------------------------------------------------
__global__ void __launch_bounds__(256)
kC(const float* __restrict__ x,
   const float* __restrict__ g1, const float* __restrict__ be1,
   const float* __restrict__ mu1, const float* __restrict__ va1,
   const float* __restrict__ w3, const float* __restrict__ b3,
   float* __restrict__ out)
{
    extern __shared__ char smem[];
    const uint32_t sb = smem_to_u32(smem);
    float* s1c = (float*)(smem + PAR);
    float* t1c = s1c + 64; float* b3c = t1c + 64;

    const int tid = threadIdx.x, lane = tid & 31, wid = tid >> 5;
    const int m0 = blockIdx.y * 128;
    const int c0 = blockIdx.x * 64;

    if (tid < 64) {
        int c = c0 + tid;
        float s = g1[c] * rsqrtf(va1[c] + EPS);
        s1c[tid] = s; t1c[tid] = be1[c] - mu1[c] * s; b3c[tid] = b3[c];
    }
    // A tile: pre-split h4 rows
    {
        const int row = tid >> 1, half = tid & 1;
        const uint4* hp = reinterpret_cast<const uint4*>(g_h4hi + (size_t)(m0 + row) * MID + half * 32);
        const uint4* lp = reinterpret_cast<const uint4*>(g_h4lo + (size_t)(m0 + row) * MID + half * 32);
        #pragma unroll
        for (int q = 0; q < 4; q++) {
            int bo = row * ASTRIDE + half * 64 + q * 16;
            *(uint4*)(smem + AHI + bo) = hp[q];
            *(uint4*)(smem + ALO + bo) = lp[q];
        }
    }
    build_B(smem, w3 + c0, CIN, tid);
    __syncthreads();

    const uint32_t aoff = a_off(wid * 16, lane), boff = b_off(lane);
    float acc[8][4] = {};
    gemm_chunk(sb, aoff, boff, acc);

    // Epilogue: + b3 + shortcut, fp32 out
    const int r0 = m0 + wid * 16 + (lane >> 2);
    #pragma unroll
    for (int nt = 0; nt < 8; nt++) {
        int lc = nt * 8 + (lane & 3) * 2;
        int c = c0 + lc;
        #pragma unroll
        for (int rr = 0; rr < 2; rr++) {
            int r = r0 + rr * 8;
            float2 xv = *reinterpret_cast<const float2*>(x + (size_t)r * CIN + c);
            float o0 = acc[nt][rr*2+0] + b3c[lc]   + fmaxf(xv.x * s1c[lc]   + t1c[lc],   0.0f);
            float o1 = acc[nt][rr*2+1] + b3c[lc+1] + fmaxf(xv.y * s1c[lc+1] + t1c[lc+1], 0.0f);
            *reinterpret_cast<float2*>(out + (size_t)r * CIN + c) = make_float2(o0, o1);
        }
    }
}

// ---------------------------------------------------------------------------
extern "C" void kernel_launch(void* const* d_in, const int* in_sizes, int n_in,
                              void* d_out, int out_size)
{
    const float* x     = (const float*)d_in[0];
    const float* bn1_g = (const float*)d_in[1];
    const float* bn1_b = (const float*)d_in[2];
    const float* bn1_m = (const float*)d_in[3];
    const float* bn1_v = (const float*)d_in[4];
    const float* w1    = (const float*)d_in[5];
    const float* b1    = (const float*)d_in[6];
    const float* bn2_g = (const float*)d_in[7];
    const float* bn2_b = (const float*)d_in[8];
    const float* bn2_m = (const float*)d_in[9];
    const float* bn2_v = (const float*)d_in[10];
    const float* w2    = (const float*)d_in[11];
    const float* b2    = (const float*)d_in[12];
    const float* bn3_g = (const float*)d_in[13];
    const float* bn3_b = (const float*)d_in[14];
    const float* bn3_m = (const float*)d_in[15];
    const float* bn3_v = (const float*)d_in[16];
    const float* w3    = (const float*)d_in[17];
    const float* b3    = (const float*)d_in[18];
    const int*   nbr   = (const int*)d_in[19];
    const void*  msk   = (const void*)d_in[20];
    float* out = (float*)d_out;

    const int SMA = PAR + (256 + 256 + 64 + 64) * 4;
    const int SMB = PAR + (64 + 64) * 4;
    const int SMC = PAR + (64 + 64 + 64) * 4;
    cudaFuncSetAttribute(kA, cudaFuncAttributeMaxDynamicSharedMemorySize, SMA);
    cudaFuncSetAttribute(kB, cudaFuncAttributeMaxDynamicSharedMemorySize, SMB);
    cudaFuncSetAttribute(kC, cudaFuncAttributeMaxDynamicSharedMemorySize, SMC);

    kDetect<<<1, 1>>>((const unsigned char*)msk);
    kA<<<NROWS / 128, 256, SMA>>>(x, bn1_g, bn1_b, bn1_m, bn1_v, w1, b1,
                                  bn2_g, bn2_b, bn2_m, bn2_v);
    kB<<<NROWS / 128, 256, SMB>>>(w2, b2, bn3_g, bn3_b, bn3_m, bn3_v, nbr, msk);
    kC<<<dim3(4, NROWS / 128), 256, SMC>>>(x, bn1_g, bn1_b, bn1_m, bn1_v,
                                           w3, b3, out);
    (void)in_sizes; (void)n_in; (void)out_size;
}